// round 7
// baseline (speedup 1.0000x reference)
#include <cuda_runtime.h>
#include <cstdint>
#include <math.h>

#define NBINS 15
#define C_DIM 1000
#define C4    250               // float4 per row
#define WARPS_PER_BLOCK 8
#define THREADS (WARPS_PER_BLOCK * 32)
#define GRID_BLOCKS 304         // 152 SMs x 2 CTAs resident (128-reg kernel)
#define ROWS_PER_WARP 4
#define BATCH_ROWS (WARPS_PER_BLOCK * ROWS_PER_WARP)   // 32 rows per stolen batch

// Global accumulators + work queue (allocation-free scratch). Zeroed at module
// load for the first (correctness) call; the finishing block resets them so
// every graph replay starts clean.
__device__ double g_cnt[NBINS];
__device__ double g_conf[NBINS];
__device__ double g_acc[NBINS];
__device__ unsigned int g_ticket = 0;
__device__ unsigned int g_work = 0;

__device__ __forceinline__ float ex2f(float x) {
    float r;
    asm("ex2.approx.f32 %0, %1;" : "=f"(r) : "f"(x));
    return r;
}
__device__ __forceinline__ unsigned f2ord(float f) {
    int i = __float_as_int(f);
    return (unsigned)(i ^ ((i >> 31) | 0x80000000));
}
__device__ __forceinline__ float ord2f(unsigned u) {
    int i = (int)(u ^ ((((int)~u) >> 31) | 0x80000000));
    return __int_as_float(i);
}

__device__ __forceinline__ void load_row(float4 (&v)[8],
                                         const float* __restrict__ logits,
                                         int row, int lane) {
    const float4* rp = reinterpret_cast<const float4*>(logits + (size_t)row * C_DIM) + lane;
    #pragma unroll
    for (int k = 0; k < 8; k++) {
        if (lane + 32 * k < C4) v[k] = rp[32 * k];
        else v[k] = make_float4(-1e30f, -1e30f, -1e30f, -1e30f);
    }
}

__device__ __forceinline__ void process_row(const float4 (&v)[8],
                                            const int* __restrict__ labels,
                                            int row, int lane,
                                            float* s_cnt, float* s_conf, float* s_acc) {
    // Prefetch label early: its latency hides under the max/exp math below.
    int lab = 0;
    if (lane == 0) lab = __ldg(labels + row);

    // Per-float4 maxes, tree to lane max, warp max via integer redux.
    float m4[8];
    #pragma unroll
    for (int k = 0; k < 8; k++)
        m4[k] = fmaxf(fmaxf(v[k].x, v[k].y), fmaxf(v[k].z, v[k].w));
    float a0 = fmaxf(m4[0], m4[1]), a1 = fmaxf(m4[2], m4[3]);
    float a2 = fmaxf(m4[4], m4[5]), a3 = fmaxf(m4[6], m4[7]);
    float m  = fmaxf(fmaxf(a0, a1), fmaxf(a2, a3));
    float wm = ord2f(__reduce_max_sync(0xffffffffu, f2ord(m)));

    // Argmax drill-down: smallest index equal to wm.
    int mi = 0x7fffffff;
    #pragma unroll
    for (int k = 7; k >= 0; k--) {
        if (m4[k] == wm) {
            int base = 4 * (lane + 32 * k);
            if (v[k].w == wm) mi = base + 3;
            if (v[k].z == wm) mi = base + 2;
            if (v[k].y == wm) mi = base + 1;
            if (v[k].x == wm) mi = base;
        }
    }
    unsigned wmi = __reduce_min_sync(0xffffffffu, (unsigned)mi);

    // sum exp(x - wm) = 2^(x*log2e + b); padding (-1e30) underflows to 0.
    const float L = 1.4426950408889634f;
    const float b = -wm * L;
    float s0 = 0.f, s1 = 0.f, s2 = 0.f, s3 = 0.f;
    #pragma unroll
    for (int k = 0; k < 8; k++) {
        s0 += ex2f(fmaf(v[k].x, L, b));
        s1 += ex2f(fmaf(v[k].y, L, b));
        s2 += ex2f(fmaf(v[k].z, L, b));
        s3 += ex2f(fmaf(v[k].w, L, b));
    }
    float s = (s0 + s1) + (s2 + s3);
    #pragma unroll
    for (int off = 16; off; off >>= 1)
        s += __shfl_xor_sync(0xffffffffu, s, off);

    if (lane == 0) {
        float conf = 1.0f / s;   // = exp(wm - lse), > 0 so bin >= 0, valid=1
        int bin = 0;
        #pragma unroll
        for (int q = 1; q < NBINS; q++)
            bin += (conf > ((float)q / (float)NBINS)) ? 1 : 0;
        float acc = (lab == (int)wmi) ? 1.0f : 0.0f;
        atomicAdd(&s_cnt[bin],  1.0f);
        atomicAdd(&s_conf[bin], conf);
        atomicAdd(&s_acc[bin],  acc);
    }
}

__global__ __launch_bounds__(THREADS, 2) void ece_ws_kernel(
    const float* __restrict__ logits,
    const int* __restrict__ labels,
    int n_rows,
    float* __restrict__ out)
{
    __shared__ float s_cnt[NBINS];
    __shared__ float s_conf[NBINS];
    __shared__ float s_acc[NBINS];
    __shared__ int   s_b[2];
    __shared__ bool  s_is_last;

    const int tid  = threadIdx.x;
    const int lane = tid & 31;
    const int warp = tid >> 5;

    if (tid < NBINS) {
        s_cnt[tid]  = 0.0f;
        s_conf[tid] = 0.0f;
        s_acc[tid]  = 0.0f;
    }
    if (tid == 0) s_b[0] = (int)atomicAdd(&g_work, 1u);
    __syncthreads();

    const int n_batches = (n_rows + BATCH_ROWS - 1) / BATCH_ROWS;
    int slot = 0;
    int bidx = s_b[0];

    float4 A[8], B[8];

    while (bidx < n_batches) {
        // Prefetch the NEXT batch id; latency hides behind this batch's work.
        if (tid == 0) s_b[slot ^ 1] = (int)atomicAdd(&g_work, 1u);

        const int r0 = bidx * BATCH_ROWS + warp * ROWS_PER_WARP;

        // 4 rows, double-buffered: load r+1 while processing r.
        bool v0 = r0 < n_rows;
        if (v0) load_row(A, logits, r0, lane);

        bool v1 = r0 + 1 < n_rows;
        if (v1) load_row(B, logits, r0 + 1, lane);
        if (v0) process_row(A, labels, r0, lane, s_cnt, s_conf, s_acc);

        bool v2 = r0 + 2 < n_rows;
        if (v2) load_row(A, logits, r0 + 2, lane);
        if (v1) process_row(B, labels, r0 + 1, lane, s_cnt, s_conf, s_acc);

        bool v3 = r0 + 3 < n_rows;
        if (v3) load_row(B, logits, r0 + 3, lane);
        if (v2) process_row(A, labels, r0 + 2, lane, s_cnt, s_conf, s_acc);

        if (v3) process_row(B, labels, r0 + 3, lane, s_cnt, s_conf, s_acc);

        __syncthreads();           // s_b[slot^1] now valid for everyone
        slot ^= 1;
        bidx = s_b[slot];
    }

    __syncthreads();
    if (tid < NBINS) {
        float c = s_cnt[tid];
        if (c != 0.0f) {
            atomicAdd(&g_cnt[tid],  (double)c);
            atomicAdd(&g_conf[tid], (double)s_conf[tid]);
            atomicAdd(&g_acc[tid],  (double)s_acc[tid]);
        }
    }

    // Last-block-done ticket -> fused finalize + reset for graph replays.
    __threadfence();
    __syncthreads();
    if (tid == 0) {
        unsigned int t = atomicAdd(&g_ticket, 1u);
        s_is_last = (t == gridDim.x - 1);
    }
    __syncthreads();

    if (s_is_last && warp == 0) {
        double term_ece = 0.0, term_acc = 0.0;
        if (lane < NBINS) {
            double cnt = g_cnt[lane];
            if (cnt > 0.0) {
                double prop = cnt / (double)n_rows;
                double avg_conf = g_conf[lane] / cnt;
                double avg_acc  = g_acc[lane]  / cnt;
                term_ece = fabs(avg_conf - avg_acc) * prop;
                term_acc = avg_acc * prop;
            }
            g_cnt[lane]  = 0.0;
            g_conf[lane] = 0.0;
            g_acc[lane]  = 0.0;
        }
        #pragma unroll
        for (int off = 16; off; off >>= 1) {
            term_ece += __shfl_xor_sync(0xffffffffu, term_ece, off);
            term_acc += __shfl_xor_sync(0xffffffffu, term_acc, off);
        }
        if (lane == 0) {
            out[0] = (float)(term_ece * 100.0);
            out[1] = (float)(term_acc * 100.0);
            g_ticket = 0;
            g_work = 0;
        }
    }
}

extern "C" void kernel_launch(void* const* d_in, const int* in_sizes, int n_in,
                              void* d_out, int out_size) {
    const float* logits = (const float*)d_in[0];
    const int*   labels = (const int*)d_in[1];
    float* out = (float*)d_out;

    int n_rows = in_sizes[1];  // labels element count = N

    ece_ws_kernel<<<GRID_BLOCKS, THREADS>>>(logits, labels, n_rows, out);
}

// round 8
// speedup vs baseline: 1.1335x; 1.1335x over previous
#include <cuda_runtime.h>
#include <cstdint>
#include <math.h>

#define NBINS 15
#define C_DIM 1000
#define C4    250               // float4 per row
#define WARPS_PER_BLOCK 8
#define THREADS (WARPS_PER_BLOCK * 32)
#define GRID_BLOCKS 304         // 152 SMs x 2 CTAs resident (128-reg kernel)
#define TOTAL_WARPS (GRID_BLOCKS * WARPS_PER_BLOCK)   // 2432

// Global accumulators (allocation-free scratch). Zeroed at module load for the
// first (correctness) call; the finishing block resets them for each replay.
__device__ double g_cnt[NBINS];
__device__ double g_conf[NBINS];
__device__ double g_acc[NBINS];
__device__ unsigned int g_ticket = 0;

__device__ __forceinline__ float ex2f(float x) {
    float r;
    asm("ex2.approx.f32 %0, %1;" : "=f"(r) : "f"(x));
    return r;
}
__device__ __forceinline__ unsigned f2ord(float f) {
    int i = __float_as_int(f);
    return (unsigned)(i ^ ((i >> 31) | 0x80000000));
}
__device__ __forceinline__ float ord2f(unsigned u) {
    int i = (int)(u ^ ((((int)~u) >> 31) | 0x80000000));
    return __int_as_float(i);
}

__device__ __forceinline__ void load_row(float4 (&v)[8],
                                         const float* __restrict__ logits,
                                         int row, int lane) {
    const float4* rp = reinterpret_cast<const float4*>(logits + (size_t)row * C_DIM) + lane;
    #pragma unroll
    for (int k = 0; k < 8; k++) {
        if (lane + 32 * k < C4) v[k] = rp[32 * k];
        else v[k] = make_float4(-1e30f, -1e30f, -1e30f, -1e30f);
    }
}

__device__ __forceinline__ void process_row(const float4 (&v)[8],
                                            const int* __restrict__ labels,
                                            int row, int lane,
                                            float* s_cnt, float* s_conf, float* s_acc) {
    // Prefetch label at the top: latency hides under the max/exp math.
    int lab = 0;
    if (lane == 0) lab = __ldg(labels + row);

    // Per-float4 maxes, tree to lane max, warp max via integer redux.
    float m4[8];
    #pragma unroll
    for (int k = 0; k < 8; k++)
        m4[k] = fmaxf(fmaxf(v[k].x, v[k].y), fmaxf(v[k].z, v[k].w));
    float a0 = fmaxf(m4[0], m4[1]), a1 = fmaxf(m4[2], m4[3]);
    float a2 = fmaxf(m4[4], m4[5]), a3 = fmaxf(m4[6], m4[7]);
    float m  = fmaxf(fmaxf(a0, a1), fmaxf(a2, a3));
    float wm = ord2f(__reduce_max_sync(0xffffffffu, f2ord(m)));

    // Argmax drill-down: smallest index equal to wm.
    int mi = 0x7fffffff;
    #pragma unroll
    for (int k = 7; k >= 0; k--) {
        if (m4[k] == wm) {
            int base = 4 * (lane + 32 * k);
            if (v[k].w == wm) mi = base + 3;
            if (v[k].z == wm) mi = base + 2;
            if (v[k].y == wm) mi = base + 1;
            if (v[k].x == wm) mi = base;
        }
    }
    unsigned wmi = __reduce_min_sync(0xffffffffu, (unsigned)mi);

    // sum exp(x - wm) = 2^(x*log2e + b); padding (-1e30) underflows to 0.
    const float L = 1.4426950408889634f;
    const float b = -wm * L;
    float s0 = 0.f, s1 = 0.f, s2 = 0.f, s3 = 0.f;
    #pragma unroll
    for (int k = 0; k < 8; k++) {
        s0 += ex2f(fmaf(v[k].x, L, b));
        s1 += ex2f(fmaf(v[k].y, L, b));
        s2 += ex2f(fmaf(v[k].z, L, b));
        s3 += ex2f(fmaf(v[k].w, L, b));
    }
    float s = (s0 + s1) + (s2 + s3);
    #pragma unroll
    for (int off = 16; off; off >>= 1)
        s += __shfl_xor_sync(0xffffffffu, s, off);

    if (lane == 0) {
        float conf = 1.0f / s;   // = exp(wm - lse), > 0 so bin >= 0, valid=1
        int bin = 0;
        #pragma unroll
        for (int q = 1; q < NBINS; q++)
            bin += (conf > ((float)q / (float)NBINS)) ? 1 : 0;
        float acc = (lab == (int)wmi) ? 1.0f : 0.0f;
        atomicAdd(&s_cnt[bin],  1.0f);
        atomicAdd(&s_conf[bin], conf);
        atomicAdd(&s_acc[bin],  acc);
    }
}

__global__ __launch_bounds__(THREADS, 2) void ece_seq_kernel(
    const float* __restrict__ logits,
    const int* __restrict__ labels,
    int n_rows,
    float* __restrict__ out)
{
    __shared__ float s_cnt[NBINS];
    __shared__ float s_conf[NBINS];
    __shared__ float s_acc[NBINS];
    __shared__ bool  s_is_last;

    const int tid  = threadIdx.x;
    const int lane = tid & 31;
    const int warp = tid >> 5;

    if (tid < NBINS) {
        s_cnt[tid]  = 0.0f;
        s_conf[tid] = 0.0f;
        s_acc[tid]  = 0.0f;
    }
    __syncthreads();

    // Contiguous per-warp span: warp g streams rows [g*rpw, (g+1)*rpw) in
    // order -> sequential DRAM pages per stream instead of 32 MB jumps.
    const int gw  = blockIdx.x * WARPS_PER_BLOCK + warp;
    const int rpw = (n_rows + TOTAL_WARPS - 1) / TOTAL_WARPS;   // 27 for 65536
    int row       = gw * rpw;
    const int rend = min(row + rpw, n_rows);

    // Software-pipelined double buffer: next row's 8 LDG.128 in flight while
    // the current row's math runs. No block barriers anywhere in the loop.
    float4 A[8], B[8];
    bool valid = row < rend;
    if (valid) load_row(A, logits, row, lane);
    while (valid) {
        int nrow = row + 1;
        bool nvalid = nrow < rend;
        if (nvalid) load_row(B, logits, nrow, lane);
        process_row(A, labels, row, lane, s_cnt, s_conf, s_acc);
        row = nrow; valid = nvalid;
        if (!valid) break;

        nrow = row + 1;
        nvalid = nrow < rend;
        if (nvalid) load_row(A, logits, nrow, lane);
        process_row(B, labels, row, lane, s_cnt, s_conf, s_acc);
        row = nrow; valid = nvalid;
    }

    __syncthreads();
    if (tid < NBINS) {
        float c = s_cnt[tid];
        if (c != 0.0f) {
            atomicAdd(&g_cnt[tid],  (double)c);
            atomicAdd(&g_conf[tid], (double)s_conf[tid]);
            atomicAdd(&g_acc[tid],  (double)s_acc[tid]);
        }
    }

    // Last-block-done ticket -> fused finalize + reset for graph replays.
    __threadfence();
    __syncthreads();
    if (tid == 0) {
        unsigned int t = atomicAdd(&g_ticket, 1u);
        s_is_last = (t == gridDim.x - 1);
    }
    __syncthreads();

    if (s_is_last && warp == 0) {
        double term_ece = 0.0, term_acc = 0.0;
        if (lane < NBINS) {
            double cnt = g_cnt[lane];
            if (cnt > 0.0) {
                double prop = cnt / (double)n_rows;
                double avg_conf = g_conf[lane] / cnt;
                double avg_acc  = g_acc[lane]  / cnt;
                term_ece = fabs(avg_conf - avg_acc) * prop;
                term_acc = avg_acc * prop;
            }
            g_cnt[lane]  = 0.0;
            g_conf[lane] = 0.0;
            g_acc[lane]  = 0.0;
        }
        #pragma unroll
        for (int off = 16; off; off >>= 1) {
            term_ece += __shfl_xor_sync(0xffffffffu, term_ece, off);
            term_acc += __shfl_xor_sync(0xffffffffu, term_acc, off);
        }
        if (lane == 0) {
            out[0] = (float)(term_ece * 100.0);
            out[1] = (float)(term_acc * 100.0);
            g_ticket = 0;
        }
    }
}

extern "C" void kernel_launch(void* const* d_in, const int* in_sizes, int n_in,
                              void* d_out, int out_size) {
    const float* logits = (const float*)d_in[0];
    const int*   labels = (const int*)d_in[1];
    float* out = (float*)d_out;

    int n_rows = in_sizes[1];  // labels element count = N

    ece_seq_kernel<<<GRID_BLOCKS, THREADS>>>(logits, labels, n_rows, out);
}